// round 13
// baseline (speedup 1.0000x reference)
#include <cuda_runtime.h>
#include <cuda_bf16.h>
#include <cstdint>
#include <cstddef>

// Problem constants
#define BB 2
#define SS 2048
#define DD 1024
#define HH 16
#define HDIM 64
#define MTOT (BB * SS) // 4096

#define ACT ((size_t)MTOT * DD)  // 4194304 elements
#define WN  ((size_t)DD * DD)    // 1048576 elements

// ---------------------------------------------------------------------------
// Scratch (device globals). hi/lo pairs are contiguous: lo = hi + ACT (or WN).
// ---------------------------------------------------------------------------
__device__ int g_idx[MTOT];
__device__ int g_cnt[BB];
__device__ __nv_bfloat16 g_q[2 * MTOT * DD];
__device__ __nv_bfloat16 g_k[2 * MTOT * DD];
__device__ __nv_bfloat16 g_v[2 * MTOT * DD];
__device__ __nv_bfloat16 g_W[4][2 * DD * DD];
__device__ __nv_bfloat16 g_pq[2 * MTOT * DD];
__device__ __nv_bfloat16 g_pk[2 * MTOT * DD];
__device__ __nv_bfloat16 g_pv[2 * MTOT * DD];
__device__ __nv_bfloat16 g_a[2 * MTOT * DD];

// ---------------------------------------------------------------------------
// PTX helpers
// ---------------------------------------------------------------------------
__device__ __forceinline__ void cp16(unsigned dst, const void* src) {
    asm volatile("cp.async.cg.shared.global [%0], [%1], 16;" :: "r"(dst), "l"(src));
}
__device__ __forceinline__ void cp_commit() { asm volatile("cp.async.commit_group;"); }
__device__ __forceinline__ void cp_wait0()  { asm volatile("cp.async.wait_group 0;" ::: "memory"); }

__device__ __forceinline__ void ldmx4(uint32_t* r, uint32_t addr) {
    asm volatile("ldmatrix.sync.aligned.m8n8.x4.shared.b16 {%0,%1,%2,%3}, [%4];"
                 : "=r"(r[0]), "=r"(r[1]), "=r"(r[2]), "=r"(r[3]) : "r"(addr));
}
__device__ __forceinline__ void ldmx4t(uint32_t* r, uint32_t addr) {
    asm volatile("ldmatrix.sync.aligned.m8n8.x4.trans.shared.b16 {%0,%1,%2,%3}, [%4];"
                 : "=r"(r[0]), "=r"(r[1]), "=r"(r[2]), "=r"(r[3]) : "r"(addr));
}
__device__ __forceinline__ void mma_bf16(float* d, const uint32_t* a, const uint32_t* b) {
    asm volatile(
        "mma.sync.aligned.m16n8k16.row.col.f32.bf16.bf16.f32 "
        "{%0,%1,%2,%3}, {%4,%5,%6,%7}, {%8,%9}, {%0,%1,%2,%3};"
        : "+f"(d[0]), "+f"(d[1]), "+f"(d[2]), "+f"(d[3])
        : "r"(a[0]), "r"(a[1]), "r"(a[2]), "r"(a[3]), "r"(b[0]), "r"(b[1]));
}
__device__ __forceinline__ uint32_t pack_bf16(float a, float b) {
    __nv_bfloat162 v(__float2bfloat16(a), __float2bfloat16(b));
    return *(uint32_t*)&v;
}
__device__ __forceinline__ float ex2(float x) {
    float r;
    asm("ex2.approx.f32 %0, %1;" : "=f"(r) : "f"(x));
    return r;
}

// ---------------------------------------------------------------------------
// Kernel: batched fp32 -> bf16 (hi, lo) split; blockIdx.y selects tensor
// ---------------------------------------------------------------------------
struct ConvArgs {
    const float* src[4];
    __nv_bfloat16* hi[4];
    __nv_bfloat16* lo[4];
};

__global__ __launch_bounds__(256) void conv_split_multi(ConvArgs a, int n8)
{
    int i = blockIdx.x * blockDim.x + threadIdx.x;
    if (i >= n8) return;
    const int y = blockIdx.y;
    const float* x = a.src[y];
    float4 v0 = ((const float4*)x)[2 * i];
    float4 v1 = ((const float4*)x)[2 * i + 1];
    float f[8] = {v0.x, v0.y, v0.z, v0.w, v1.x, v1.y, v1.z, v1.w};
    uint32_t hp[4], lp[4];
#pragma unroll
    for (int j = 0; j < 4; j++) {
        __nv_bfloat16 h0 = __float2bfloat16(f[2 * j]);
        __nv_bfloat16 h1 = __float2bfloat16(f[2 * j + 1]);
        __nv_bfloat162 hv(h0, h1);
        hp[j] = *(uint32_t*)&hv;
        lp[j] = pack_bf16(f[2 * j] - __bfloat162float(h0),
                          f[2 * j + 1] - __bfloat162float(h1));
    }
    ((uint4*)a.hi[y])[i] = make_uint4(hp[0], hp[1], hp[2], hp[3]);
    ((uint4*)a.lo[y])[i] = make_uint4(lp[0], lp[1], lp[2], lp[3]);
}

// ---------------------------------------------------------------------------
// Kernel 1: deterministic mask compaction
// ---------------------------------------------------------------------------
__global__ __launch_bounds__(1024) void build_idx_kernel(
    const int* __restrict__ kp, const int* __restrict__ am,
    int* __restrict__ idx, int* __restrict__ counts)
{
    __shared__ int ssum[1024];
    const int b = blockIdx.x;
    const int t = threadIdx.x;
    const int base = b * SS;
    const int s0 = 2 * t, s1 = 2 * t + 1;
    int v0 = (kp[base + s0] == 0 && am[base + s0] == 0) ? 1 : 0;
    int v1 = (kp[base + s1] == 0 && am[base + s1] == 0) ? 1 : 0;
    ssum[t] = v0 + v1;
    __syncthreads();
    for (int off = 1; off < 1024; off <<= 1) {
        int add = (t >= off) ? ssum[t - off] : 0;
        int val = ssum[t];
        __syncthreads();
        ssum[t] = val + add;
        __syncthreads();
    }
    int excl = ssum[t] - (v0 + v1);
    if (v0) idx[base + excl]      = base + s0;
    if (v1) idx[base + excl + v0] = base + s1;
    if (t == 1023) counts[b] = ssum[1023];
}

// ---------------------------------------------------------------------------
// Kernel 2: HMMA GEMM, tile 256x128, BK=64, 512 threads (16 warps, 32x64/warp)
// 2-stage smem pipeline, 96KB/stage. grid.z selects operand set.
// MMA issue is product-major: consecutive MMAs hit different accumulators
// (dependent-distance 4) so HMMA RAW latency is hidden at 4 warps/SMSP.
// ---------------------------------------------------------------------------
#define GSTAGE2 98304
#define GSM2_BYTES (2 * GSTAGE2)

__global__ __launch_bounds__(512, 1) void gemm_mma_kernel(
    const __nv_bfloat16* __restrict__ A0, const __nv_bfloat16* __restrict__ A1,
    const __nv_bfloat16* __restrict__ A2,
    const __nv_bfloat16* __restrict__ Wb,
    const float* __restrict__ b0, const float* __restrict__ b1,
    const float* __restrict__ b2,
    float s0,
    float* __restrict__ Cf,
    __nv_bfloat16* __restrict__ C0, __nv_bfloat16* __restrict__ C1,
    __nv_bfloat16* __restrict__ C2,
    const int* __restrict__ gather, const int* __restrict__ counts, int gmask)
{
    extern __shared__ char smem[];
    const uint32_t sb = (uint32_t)__cvta_generic_to_shared(smem);
    const int z = blockIdx.z;
    const __nv_bfloat16* Ahi = (z == 0) ? A0 : (z == 1) ? A1 : A2;
    const __nv_bfloat16* Bhi = Wb + (size_t)z * 2 * WN;
    const float* bias = (z == 0) ? b0 : (z == 1) ? b1 : b2;
    __nv_bfloat16* Chi = (z == 0) ? C0 : (z == 1) ? C1 : C2;
    const float scale = (z == 0) ? s0 : 1.0f;
    const bool useG = ((gmask >> z) & 1) != 0;

    const int nBase = blockIdx.x * 128;
    const int mBase = blockIdx.y * 256;
    int cnt = 0;
    if (useG) {
        cnt = counts[mBase >> 11];
        if ((mBase & 2047) >= cnt) return;
    }
    const int t = threadIdx.x;
    const int wid = t >> 5, lane = t & 31;
    const int wm = wid >> 1;
    const int wn = wid & 1;

    const int sRow = t >> 1, uA = (t & 1) * 4;
    int srcRow;
    {
        int m = mBase + sRow;
        if (useG) {
            bool ok = (m & 2047) < cnt;
            srcRow = ok ? gather[m] : ((m >> 11) * SS);
        } else {
            srcRow = m;
        }
    }
    const __nv_bfloat16* aHp = Ahi + (size_t)srcRow * DD;
    const int sRowW = t >> 2, uW = (t & 3) * 2;
    const __nv_bfloat16* bHp = Bhi + (size_t)(nBase + sRowW) * DD;

    const int g  = lane >> 3;
    const int lr = lane & 7;
    const uint32_t rowA = wm * 32 + (g & 1) * 8 + lr;
    const uint32_t rxa  = rowA & 7;
    const uint32_t aoff = rowA * 128;
    const int aU = g >> 1;
    const uint32_t rowB = wn * 64 + (g >> 1) * 8 + lr;
    const uint32_t rxb  = rowB & 7;
    const uint32_t boff = rowB * 128;
    const int bU = g & 1;

    float acc[2][8][4];
#pragma unroll
    for (int mt = 0; mt < 2; mt++)
#pragma unroll
        for (int j = 0; j < 8; j++)
#pragma unroll
            for (int r = 0; r < 4; r++) acc[mt][j][r] = 0.f;

    auto stage = [&](int s, int k0) {
        const uint32_t bb = sb + s * GSTAGE2;
#pragma unroll
        for (int i = 0; i < 4; i++) {
            int u = uA + i;
            uint32_t sw = sRow * 128 + ((u ^ (sRow & 7)) << 4);
            cp16(bb +         sw, aHp + k0 + u * 8);
            cp16(bb + 32768 + sw, aHp + ACT + k0 + u * 8);
        }
#pragma unroll
        for (int i = 0; i < 2; i++) {
            int u = uW + i;
            uint32_t sw = sRowW * 128 + ((u ^ (sRowW & 7)) << 4);
            cp16(bb + 65536 + sw, bHp + k0 + u * 8);
            cp16(bb + 81920 + sw, bHp + WN + k0 + u * 8);
        }
        cp_commit();
    };
    stage(0, 0);

    for (int c = 0; c < 16; c++) {
        cp_wait0();
        __syncthreads();
        if (c + 1 < 16) stage((c + 1) & 1, (c + 1) * 64);

        const uint32_t base = sb + (c & 1) * GSTAGE2;
#pragma unroll
        for (int ks = 0; ks < 4; ks++) {
            uint32_t ah[2][4], al[2][4];
#pragma unroll
            for (int mt = 0; mt < 2; mt++) {
                uint32_t sw = ((2 * ks + aU) ^ rxa) << 4;
                ldmx4(ah[mt], base +         aoff + mt * 2048 + sw);
                ldmx4(al[mt], base + 32768 + aoff + mt * 2048 + sw);
            }
#pragma unroll
            for (int jp = 0; jp < 4; jp++) {
                uint32_t sw = ((2 * ks + bU) ^ rxb) << 4;
                uint32_t rh[4], rl[4];
                ldmx4(rh, base + 65536 + boff + jp * 2048 + sw);
                ldmx4(rl, base + 81920 + boff + jp * 2048 + sw);
                // product-major: dependent MMAs on the same accumulator are 4 apart
                mma_bf16(acc[0][2 * jp],     ah[0], rh);
                mma_bf16(acc[1][2 * jp],     ah[1], rh);
                mma_bf16(acc[0][2 * jp + 1], ah[0], rh + 2);
                mma_bf16(acc[1][2 * jp + 1], ah[1], rh + 2);
                mma_bf16(acc[0][2 * jp],     ah[0], rl);
                mma_bf16(acc[1][2 * jp],     ah[1], rl);
                mma_bf16(acc[0][2 * jp + 1], ah[0], rl + 2);
                mma_bf16(acc[1][2 * jp + 1], ah[1], rl + 2);
                mma_bf16(acc[0][2 * jp],     al[0], rh);
                mma_bf16(acc[1][2 * jp],     al[1], rh);
                mma_bf16(acc[0][2 * jp + 1], al[0], rh + 2);
                mma_bf16(acc[1][2 * jp + 1], al[1], rh + 2);
            }
        }
        __syncthreads();
    }

#pragma unroll
    for (int mt = 0; mt < 2; mt++) {
        int m0 = mBase + wm * 32 + mt * 16 + (lane >> 2);
        int m1 = m0 + 8;
        bool ok0 = true, ok1 = true;
        if (useG) {
            ok0 = (m0 & 2047) < cnt;
            ok1 = (m1 & 2047) < cnt;
        }
#pragma unroll
        for (int j = 0; j < 8; j++) {
            int n = nBase + wn * 64 + j * 8 + 2 * (lane & 3);
            float b0v = bias[n], b1v = bias[n + 1];
            float o00 = (acc[mt][j][0] + b0v) * scale;
            float o01 = (acc[mt][j][1] + b1v) * scale;
            float o10 = (acc[mt][j][2] + b0v) * scale;
            float o11 = (acc[mt][j][3] + b1v) * scale;
            if (Cf) {
                if (ok0) *(float2*)&Cf[(size_t)m0 * DD + n] = make_float2(o00, o01);
                if (ok1) *(float2*)&Cf[(size_t)m1 * DD + n] = make_float2(o10, o11);
            } else {
                if (ok0) {
                    __nv_bfloat16 h0 = __float2bfloat16(o00), h1 = __float2bfloat16(o01);
                    *(__nv_bfloat162*)&Chi[(size_t)m0 * DD + n] = __nv_bfloat162(h0, h1);
                    *(__nv_bfloat162*)&Chi[ACT + (size_t)m0 * DD + n] = __nv_bfloat162(
                        __float2bfloat16(o00 - __bfloat162float(h0)),
                        __float2bfloat16(o01 - __bfloat162float(h1)));
                }
                if (ok1) {
                    __nv_bfloat16 h0 = __float2bfloat16(o10), h1 = __float2bfloat16(o11);
                    *(__nv_bfloat162*)&Chi[(size_t)m1 * DD + n] = __nv_bfloat162(h0, h1);
                    *(__nv_bfloat162*)&Chi[ACT + (size_t)m1 * DD + n] = __nv_bfloat162(
                        __float2bfloat16(o10 - __bfloat162float(h0)),
                        __float2bfloat16(o11 - __bfloat162float(h1)));
                }
            }
        }
    }
}

// ---------------------------------------------------------------------------
// Kernel 3: tensor-core flash attention (streamed B fragments, 2 CTAs/SM,
// product-major MMA issue)
// ---------------------------------------------------------------------------
#define ASM_KH 0
#define ASM_KL 16384
#define ASM_VH 32768
#define ASM_VL 49152
#define ATTN_SMEM 65536

__global__ __launch_bounds__(256, 2) void attn_mma_kernel(
    const __nv_bfloat16* __restrict__ Qh_, const __nv_bfloat16* __restrict__ Ql_,
    const __nv_bfloat16* __restrict__ Kh_, const __nv_bfloat16* __restrict__ Kl_,
    const __nv_bfloat16* __restrict__ Vh_, const __nv_bfloat16* __restrict__ Vl_,
    __nv_bfloat16* __restrict__ Oh_, __nv_bfloat16* __restrict__ Ol_,
    const int* __restrict__ counts)
{
    extern __shared__ char smem[];
    const uint32_t sb = (uint32_t)__cvta_generic_to_shared(smem);
    const int qb = blockIdx.x, h = blockIdx.y, b = blockIdx.z;
    const int t = threadIdx.x, w = t >> 5, lane = t & 31;
    const int q0 = qb * 128;
    const int cnt = counts[b];
    const int nb = (cnt + 63) >> 6;
    const size_t hoff = (size_t)h * HDIM;

    const int g  = lane >> 3;
    const int lr = lane & 7;
    const uint32_t rowA = w * 16 + (g & 1) * 8 + lr;
    const uint32_t rxa  = rowA & 7;
    const uint32_t aoff = rowA * 128;
    const int aU = g >> 1;
    const uint32_t rowB = (g >> 1) * 8 + lr;
    const uint32_t rxb  = rowB & 7;
    const int bU = g & 1;
    const uint32_t rowV = (g & 1) * 8 + lr;
    const uint32_t rxv  = rowV & 7;
    const int vU = g >> 1;

    {
        const int sRowQ = t >> 1, uBQ = (t & 1) * 4;
        const __nv_bfloat16* qhp = Qh_ + (size_t)(b * SS + q0 + sRowQ) * DD + hoff;
        const __nv_bfloat16* qlp = Ql_ + (size_t)(b * SS + q0 + sRowQ) * DD + hoff;
#pragma unroll
        for (int i = 0; i < 4; i++) {
            int u = uBQ + i;
            uint32_t off = sRowQ * 128 + ((u ^ (sRowQ & 7)) << 4);
            cp16(sb + off,         qhp + u * 8);
            cp16(sb + 16384 + off, qlp + u * 8);
        }
        cp_commit();
    }
    cp_wait0();
    __syncthreads();

    uint32_t qah[4][4], qal[4][4];
#pragma unroll
    for (int ks = 0; ks < 4; ks++) {
        const uint32_t swA = ((2 * ks + aU) ^ rxa) << 4;
        ldmx4(qah[ks], sb +         aoff + swA);
        ldmx4(qal[ks], sb + 16384 + aoff + swA);
    }
    __syncthreads();

    const int sRowK = t >> 2, uBK = (t & 3) * 2;
    auto stage_kv = [&](int bufI, int kbase) {
        const size_t rb = (size_t)(b * SS + kbase + sRowK) * DD + hoff;
        const uint32_t o = bufI * 8192;
#pragma unroll
        for (int i = 0; i < 2; i++) {
            int u = uBK + i;
            uint32_t sw = sRowK * 128 + ((u ^ (sRowK & 7)) << 4);
            cp16(sb + ASM_KH + o + sw, Kh_ + rb + u * 8);
            cp16(sb + ASM_KL + o + sw, Kl_ + rb + u * 8);
            cp16(sb + ASM_VH + o + sw, Vh_ + rb + u * 8);
            cp16(sb + ASM_VL + o + sw, Vl_ + rb + u * 8);
        }
    };
    stage_kv(0, 0);
    cp_commit();

    float m0 = -1e30f, m1 = -1e30f, l0 = 0.f, l1 = 0.f;
    float oacc[8][4];
#pragma unroll
    for (int j = 0; j < 8; j++)
#pragma unroll
        for (int r = 0; r < 4; r++) oacc[j][r] = 0.f;

    int buf = 0;
    for (int kb = 0; kb < nb; kb++) {
        cp_wait0();
        __syncthreads();
        if (kb + 1 < nb) {
            stage_kv(buf ^ 1, (kb + 1) * 64);
            cp_commit();
        }

        const uint32_t tKH = sb + ASM_KH + buf * 8192;
        const uint32_t tKL = sb + ASM_KL + buf * 8192;

        // ---- S = Q K^T (hi/lo, product-major issue)
        float sacc[8][4];
#pragma unroll
        for (int j = 0; j < 8; j++)
#pragma unroll
            for (int r = 0; r < 4; r++) sacc[j][r] = 0.f;
#pragma unroll
        for (int ks = 0; ks < 4; ks++) {
#pragma unroll
            for (int jp = 0; jp < 4; jp++) {
                const uint32_t addr = (rowB + 16 * jp) * 128 + (((2 * ks + bU) ^ rxb) << 4);
                uint32_t rh[4], rl[4];
                ldmx4(rh, tKH + addr);
                ldmx4(rl, tKL + addr);
                mma_bf16(sacc[2 * jp],     qah[ks], rh);
                mma_bf16(sacc[2 * jp + 1], qah[ks], rh + 2);
                mma_bf16(sacc[2 * jp],     qah[ks], rl);
                mma_bf16(sacc[2 * jp + 1], qah[ks], rl + 2);
                mma_bf16(sacc[2 * jp],     qal[ks], rh);
                mma_bf16(sacc[2 * jp + 1], qal[ks], rh + 2);
            }
        }

        const int kcol = kb * 64 + 2 * (lane & 3);
#pragma unroll
        for (int j = 0; j < 8; j++) {
            const int kc = kcol + 8 * j;
            if (kc >= cnt)     { sacc[j][0] = -1e30f; sacc[j][2] = -1e30f; }
            if (kc + 1 >= cnt) { sacc[j][1] = -1e30f; sacc[j][3] = -1e30f; }
        }

        float rm0 = -1e30f, rm1 = -1e30f;
#pragma unroll
        for (int j = 0; j < 8; j++) {
            rm0 = fmaxf(rm0, fmaxf(sacc[j][0], sacc[j][1]));
            rm1 = fmaxf(rm1, fmaxf(sacc[j][2], sacc[j][3]));
        }
        rm0 = fmaxf(rm0, __shfl_xor_sync(0xffffffffu, rm0, 1));
        rm0 = fmaxf(rm0, __shfl_xor_sync(0xffffffffu, rm0, 2));
        rm1 = fmaxf(rm1, __shfl_xor_sync(0xffffffffu, rm1, 1));
        rm1 = fmaxf(rm1, __shfl_xor_sync(0xffffffffu, rm1, 2));
        const float nm0 = fmaxf(m0, rm0), nm1 = fmaxf(m1, rm1);
        const float c0 = ex2(m0 - nm0), c1 = ex2(m1 - nm1);
        m0 = nm0; m1 = nm1;
        float rs0 = 0.f, rs1 = 0.f;
#pragma unroll
        for (int j = 0; j < 8; j++) {
            sacc[j][0] = ex2(sacc[j][0] - nm0);
            sacc[j][1] = ex2(sacc[j][1] - nm0);
            sacc[j][2] = ex2(sacc[j][2] - nm1);
            sacc[j][3] = ex2(sacc[j][3] - nm1);
            rs0 += sacc[j][0] + sacc[j][1];
            rs1 += sacc[j][2] + sacc[j][3];
        }
        rs0 += __shfl_xor_sync(0xffffffffu, rs0, 1);
        rs0 += __shfl_xor_sync(0xffffffffu, rs0, 2);
        rs1 += __shfl_xor_sync(0xffffffffu, rs1, 1);
        rs1 += __shfl_xor_sync(0xffffffffu, rs1, 2);
        l0 = l0 * c0 + rs0;
        l1 = l1 * c1 + rs1;
#pragma unroll
        for (int j = 0; j < 8; j++) {
            oacc[j][0] *= c0; oacc[j][1] *= c0;
            oacc[j][2] *= c1; oacc[j][3] *= c1;
        }

        // ---- O += P V (hi/lo, product-major issue)
        const uint32_t tVH = sb + ASM_VH + buf * 8192;
        const uint32_t tVL = sb + ASM_VL + buf * 8192;
#pragma unroll
        for (int ks = 0; ks < 4; ks++) {
            const int nt0 = 2 * ks, nt1 = 2 * ks + 1;
            uint32_t aPh[4], aPl[4];
            {
                float p00 = sacc[nt0][0], p01 = sacc[nt0][1];
                float p02 = sacc[nt0][2], p03 = sacc[nt0][3];
                float p10 = sacc[nt1][0], p11 = sacc[nt1][1];
                float p12 = sacc[nt1][2], p13 = sacc[nt1][3];
                __nv_bfloat16 h00 = __float2bfloat16(p00), h01 = __float2bfloat16(p01);
                __nv_bfloat16 h02 = __float2bfloat16(p02), h03 = __float2bfloat16(p03);
                __nv_bfloat16 h10 = __float2bfloat16(p10), h11 = __float2bfloat16(p11);
                __nv_bfloat16 h12 = __float2bfloat16(p12), h13 = __float2bfloat16(p13);
                __nv_bfloat162 v0(h00, h01), v1(h02, h03), v2(h10, h11), v3(h12, h13);
                aPh[0] = *(uint32_t*)&v0; aPh[1] = *(uint32_t*)&v1;
                aPh[2] = *(uint32_t*)&v2; aPh[3] = *(uint32_t*)&v3;
                aPl[0] = pack_bf16(p00 - __bfloat162float(h00), p01 - __bfloat162float(h01));
                aPl[1] = pack_bf16(p02 - __bfloat162float(h02), p03 - __bfloat162float(h03));
                aPl[2] = pack_bf16(p10 - __bfloat162float(h10), p11 - __bfloat162float(h11));
                aPl[3] = pack_bf16(p12 - __bfloat162float(h12), p13 - __bfloat162float(h13));
            }
#pragma unroll
            for (int dp = 0; dp < 4; dp++) {
                const uint32_t addr = (rowV + 16 * ks) * 128 + (((2 * dp + vU) ^ rxv) << 4);
                uint32_t rvh[4], rvl[4];
                ldmx4t(rvh, tVH + addr);
                ldmx4t(rvl, tVL + addr);
                mma_bf16(oacc[2 * dp],     aPh, rvh);
                mma_bf16(oacc[2 * dp + 1], aPh, rvh + 2);
                mma_bf16(oacc[2 * dp],     aPh, rvl);
                mma_bf16(oacc[2 * dp + 1], aPh, rvl + 2);
                mma_bf16(oacc[2 * dp],     aPl, rvh);
                mma_bf16(oacc[2 * dp + 1], aPl, rvh + 2);
            }
        }
        buf ^= 1;
    }

    const float inv0 = 1.0f / l0, inv1 = 1.0f / l1;
    const int row0 = b * SS + q0 + w * 16 + (lane >> 2);
    const int row1 = row0 + 8;
    const int dbase = h * HDIM + 2 * (lane & 3);
#pragma unroll
    for (int j = 0; j < 8; j++) {
        float o00 = oacc[j][0] * inv0, o01 = oacc[j][1] * inv0;
        float o10 = oacc[j][2] * inv1, o11 = oacc[j][3] * inv1;
        __nv_bfloat16 h00 = __float2bfloat16(o00), h01 = __float2bfloat16(o01);
        __nv_bfloat16 h10 = __float2bfloat16(o10), h11 = __float2bfloat16(o11);
        size_t a0 = (size_t)row0 * DD + dbase + 8 * j;
        size_t a1 = (size_t)row1 * DD + dbase + 8 * j;
        *(__nv_bfloat162*)&Oh_[a0] = __nv_bfloat162(h00, h01);
        *(__nv_bfloat162*)&Ol_[a0] = __nv_bfloat162(
            __float2bfloat16(o00 - __bfloat162float(h00)),
            __float2bfloat16(o01 - __bfloat162float(h01)));
        *(__nv_bfloat162*)&Oh_[a1] = __nv_bfloat162(h10, h11);
        *(__nv_bfloat162*)&Ol_[a1] = __nv_bfloat162(
            __float2bfloat16(o10 - __bfloat162float(h10)),
            __float2bfloat16(o11 - __bfloat162float(h11)));
    }
}

// ---------------------------------------------------------------------------
// Launch
// ---------------------------------------------------------------------------
extern "C" void kernel_launch(void* const* d_in, const int* in_sizes, int n_in,
                              void* d_out, int out_size)
{
    (void)out_size;
    const float* qkv[3]   = {nullptr, nullptr, nullptr};
    const int*   masks[2] = {nullptr, nullptr};
    const float* Ws[4]    = {nullptr, nullptr, nullptr, nullptr};
    const float* bs[4]    = {nullptr, nullptr, nullptr, nullptr};
    int nqkv = 0, nmask = 0, nW = 0, nb = 0;
    for (int i = 0; i < n_in; i++) {
        int sz = in_sizes[i];
        if (sz == MTOT * DD && nqkv < 3)      qkv[nqkv++] = (const float*)d_in[i];
        else if (sz == MTOT && nmask < 2)     masks[nmask++] = (const int*)d_in[i];
        else if (sz == DD * DD && nW < 4)     Ws[nW++] = (const float*)d_in[i];
        else if (sz == DD && nb < 4)          bs[nb++] = (const float*)d_in[i];
    }

    static int attr_done = 0;
    if (!attr_done) {
        cudaFuncSetAttribute(gemm_mma_kernel,
                             cudaFuncAttributeMaxDynamicSharedMemorySize, GSM2_BYTES);
        cudaFuncSetAttribute(attn_mma_kernel,
                             cudaFuncAttributeMaxDynamicSharedMemorySize, ATTN_SMEM);
        attr_done = 1;
    }

    int *gidx, *gcnt;
    __nv_bfloat16 *gq, *gk, *gv, *gW, *gpq, *gpk, *gpv, *ga;
    cudaGetSymbolAddress((void**)&gidx, g_idx);
    cudaGetSymbolAddress((void**)&gcnt, g_cnt);
    cudaGetSymbolAddress((void**)&gq, g_q);
    cudaGetSymbolAddress((void**)&gk, g_k);
    cudaGetSymbolAddress((void**)&gv, g_v);
    cudaGetSymbolAddress((void**)&gW, g_W);
    cudaGetSymbolAddress((void**)&gpq, g_pq);
    cudaGetSymbolAddress((void**)&gpk, g_pk);
    cudaGetSymbolAddress((void**)&gpv, g_pv);
    cudaGetSymbolAddress((void**)&ga, g_a);

    const int N8_ACT = (int)(ACT / 8);
    const int N8_W   = (int)(WN / 8);

    build_idx_kernel<<<BB, 1024>>>(masks[0], masks[1], gidx, gcnt);

    {
        ConvArgs aa = {};
        aa.src[0] = qkv[0]; aa.hi[0] = gq; aa.lo[0] = gq + ACT;
        aa.src[1] = qkv[1]; aa.hi[1] = gk; aa.lo[1] = gk + ACT;
        aa.src[2] = qkv[2]; aa.hi[2] = gv; aa.lo[2] = gv + ACT;
        conv_split_multi<<<dim3((N8_ACT + 255) / 256, 3), 256>>>(aa, N8_ACT);

        ConvArgs wa = {};
        for (int w = 0; w < 4; w++) {
            wa.src[w] = Ws[w];
            wa.hi[w]  = gW + (size_t)w * 2 * WN;
            wa.lo[w]  = gW + (size_t)w * 2 * WN + WN;
        }
        conv_split_multi<<<dim3((N8_W + 255) / 256, 4), 256>>>(wa, N8_W);
    }

    const float QSCALE = 0.125f * 1.4426950408889634f;
    gemm_mma_kernel<<<dim3(DD / 128, MTOT / 256, 3), 512, GSM2_BYTES>>>(
        gq, gk, gv, gW, bs[0], bs[1], bs[2], QSCALE,
        nullptr, gpq, gpk, gpv, gidx, gcnt, 0b110);

    attn_mma_kernel<<<dim3(SS / 128, HH, BB), 256, ATTN_SMEM>>>(
        gpq, gpq + ACT, gpk, gpk + ACT, gpv, gpv + ACT, ga, ga + ACT, gcnt);

    gemm_mma_kernel<<<dim3(DD / 128, MTOT / 256, 1), 512, GSM2_BYTES>>>(
        ga, ga, ga, gW + (size_t)3 * 2 * WN, bs[3], bs[3], bs[3], 1.0f,
        (float*)d_out, nullptr, nullptr, nullptr, nullptr, nullptr, 0);
}

// round 14
// speedup vs baseline: 1.2675x; 1.2675x over previous
#include <cuda_runtime.h>
#include <cuda_bf16.h>
#include <cuda_fp16.h>
#include <cstdint>
#include <cstddef>

// Problem constants
#define BB 2
#define SS 2048
#define DD 1024
#define HH 16
#define HDIM 64
#define MTOT (BB * SS) // 4096

#define ACT ((size_t)MTOT * DD)  // 4194304 elements
#define WN  ((size_t)DD * DD)    // 1048576 elements

// ---------------------------------------------------------------------------
// Scratch (device globals)
// ---------------------------------------------------------------------------
__device__ int g_idx[MTOT];
__device__ int g_cnt[BB];
__device__ __half g_q[MTOT * DD];             // fp16 single-plane activations
__device__ __half g_k[MTOT * DD];
__device__ __half g_v[MTOT * DD];
__device__ __half g_W[4][2 * DD * DD];        // fp16 hi/lo weights (lo at +WN)
__device__ __nv_bfloat16 g_pq[2 * MTOT * DD]; // projected, bf16 hi/lo (attention input)
__device__ __nv_bfloat16 g_pk[2 * MTOT * DD];
__device__ __nv_bfloat16 g_pv[2 * MTOT * DD];
__device__ __half g_a[MTOT * DD];             // attention output, fp16 single-plane

// ---------------------------------------------------------------------------
// PTX helpers
// ---------------------------------------------------------------------------
__device__ __forceinline__ void cp16(unsigned dst, const void* src) {
    asm volatile("cp.async.cg.shared.global [%0], [%1], 16;" :: "r"(dst), "l"(src));
}
__device__ __forceinline__ void cp_commit() { asm volatile("cp.async.commit_group;"); }
__device__ __forceinline__ void cp_wait0()  { asm volatile("cp.async.wait_group 0;" ::: "memory"); }

__device__ __forceinline__ void ldmx4(uint32_t* r, uint32_t addr) {
    asm volatile("ldmatrix.sync.aligned.m8n8.x4.shared.b16 {%0,%1,%2,%3}, [%4];"
                 : "=r"(r[0]), "=r"(r[1]), "=r"(r[2]), "=r"(r[3]) : "r"(addr));
}
__device__ __forceinline__ void ldmx4t(uint32_t* r, uint32_t addr) {
    asm volatile("ldmatrix.sync.aligned.m8n8.x4.trans.shared.b16 {%0,%1,%2,%3}, [%4];"
                 : "=r"(r[0]), "=r"(r[1]), "=r"(r[2]), "=r"(r[3]) : "r"(addr));
}
__device__ __forceinline__ void mma_bf16(float* d, const uint32_t* a, const uint32_t* b) {
    asm volatile(
        "mma.sync.aligned.m16n8k16.row.col.f32.bf16.bf16.f32 "
        "{%0,%1,%2,%3}, {%4,%5,%6,%7}, {%8,%9}, {%0,%1,%2,%3};"
        : "+f"(d[0]), "+f"(d[1]), "+f"(d[2]), "+f"(d[3])
        : "r"(a[0]), "r"(a[1]), "r"(a[2]), "r"(a[3]), "r"(b[0]), "r"(b[1]));
}
__device__ __forceinline__ void mma_f16(float* d, const uint32_t* a, const uint32_t* b) {
    asm volatile(
        "mma.sync.aligned.m16n8k16.row.col.f32.f16.f16.f32 "
        "{%0,%1,%2,%3}, {%4,%5,%6,%7}, {%8,%9}, {%0,%1,%2,%3};"
        : "+f"(d[0]), "+f"(d[1]), "+f"(d[2]), "+f"(d[3])
        : "r"(a[0]), "r"(a[1]), "r"(a[2]), "r"(a[3]), "r"(b[0]), "r"(b[1]));
}
__device__ __forceinline__ uint32_t pack_bf16(float a, float b) {
    __nv_bfloat162 v(__float2bfloat16(a), __float2bfloat16(b));
    return *(uint32_t*)&v;
}
__device__ __forceinline__ float ex2(float x) {
    float r;
    asm("ex2.approx.f32 %0, %1;" : "=f"(r) : "f"(x));
    return r;
}

// ---------------------------------------------------------------------------
// Conv kernels: fp32 -> fp16 single (activations), fp32 -> fp16 hi/lo (weights)
// ---------------------------------------------------------------------------
struct ConvHArgs {
    const float* src[4];
    __half* dst[4];
};
__global__ __launch_bounds__(256) void conv_half_multi(ConvHArgs a, int n8)
{
    int i = blockIdx.x * blockDim.x + threadIdx.x;
    if (i >= n8) return;
    const int y = blockIdx.y;
    const float* x = a.src[y];
    float4 v0 = ((const float4*)x)[2 * i];
    float4 v1 = ((const float4*)x)[2 * i + 1];
    __half2 h0 = __floats2half2_rn(v0.x, v0.y);
    __half2 h1 = __floats2half2_rn(v0.z, v0.w);
    __half2 h2 = __floats2half2_rn(v1.x, v1.y);
    __half2 h3 = __floats2half2_rn(v1.z, v1.w);
    ((uint4*)a.dst[y])[i] = make_uint4(*(uint32_t*)&h0, *(uint32_t*)&h1,
                                       *(uint32_t*)&h2, *(uint32_t*)&h3);
}

struct ConvWArgs {
    const float* src[4];
    __half* hi[4];
    __half* lo[4];
};
__global__ __launch_bounds__(256) void conv_wsplit_multi(ConvWArgs a, int n8)
{
    int i = blockIdx.x * blockDim.x + threadIdx.x;
    if (i >= n8) return;
    const int y = blockIdx.y;
    const float* x = a.src[y];
    float4 v0 = ((const float4*)x)[2 * i];
    float4 v1 = ((const float4*)x)[2 * i + 1];
    float f[8] = {v0.x, v0.y, v0.z, v0.w, v1.x, v1.y, v1.z, v1.w};
    uint32_t hp[4], lp[4];
#pragma unroll
    for (int j = 0; j < 4; j++) {
        __half h0 = __float2half_rn(f[2 * j]);
        __half h1 = __float2half_rn(f[2 * j + 1]);
        __half l0 = __float2half_rn(f[2 * j] - __half2float(h0));
        __half l1 = __float2half_rn(f[2 * j + 1] - __half2float(h1));
        __half2 hv(h0, h1), lv(l0, l1);
        hp[j] = *(uint32_t*)&hv;
        lp[j] = *(uint32_t*)&lv;
    }
    ((uint4*)a.hi[y])[i] = make_uint4(hp[0], hp[1], hp[2], hp[3]);
    ((uint4*)a.lo[y])[i] = make_uint4(lp[0], lp[1], lp[2], lp[3]);
}

// ---------------------------------------------------------------------------
// Kernel 1: deterministic mask compaction
// ---------------------------------------------------------------------------
__global__ __launch_bounds__(1024) void build_idx_kernel(
    const int* __restrict__ kp, const int* __restrict__ am,
    int* __restrict__ idx, int* __restrict__ counts)
{
    __shared__ int ssum[1024];
    const int b = blockIdx.x;
    const int t = threadIdx.x;
    const int base = b * SS;
    const int s0 = 2 * t, s1 = 2 * t + 1;
    int v0 = (kp[base + s0] == 0 && am[base + s0] == 0) ? 1 : 0;
    int v1 = (kp[base + s1] == 0 && am[base + s1] == 0) ? 1 : 0;
    ssum[t] = v0 + v1;
    __syncthreads();
    for (int off = 1; off < 1024; off <<= 1) {
        int add = (t >= off) ? ssum[t - off] : 0;
        int val = ssum[t];
        __syncthreads();
        ssum[t] = val + add;
        __syncthreads();
    }
    int excl = ssum[t] - (v0 + v1);
    if (v0) idx[base + excl]      = base + s0;
    if (v1) idx[base + excl + v0] = base + s1;
    if (t == 1023) counts[b] = ssum[1023];
}

// ---------------------------------------------------------------------------
// Kernel 2: f16 HMMA GEMM, tile 256x128, BK=64, 512 threads.
// A = plain fp16 (one plane), W = fp16 hi/lo: C = A*Wh + A*Wl (fp32 accum).
// Staged bytes per chunk: A 32KB + W 32KB = 64KB (was 96KB), 2 stages = 128KB.
// ---------------------------------------------------------------------------
#define GSTAGE2 65536
#define GSM2_BYTES (2 * GSTAGE2)

__global__ __launch_bounds__(512, 1) void gemm_mma_kernel(
    const __half* __restrict__ A0, const __half* __restrict__ A1,
    const __half* __restrict__ A2,
    const __half* __restrict__ Wb,          // weight z at Wb + z*2*WN; lo at +WN
    const float* __restrict__ b0, const float* __restrict__ b1,
    const float* __restrict__ b2,
    float s0,
    float* __restrict__ Cf,
    __nv_bfloat16* __restrict__ C0, __nv_bfloat16* __restrict__ C1,
    __nv_bfloat16* __restrict__ C2,          // bf16 out hi; lo at +ACT
    const int* __restrict__ gather, const int* __restrict__ counts, int gmask)
{
    extern __shared__ char smem[];
    const uint32_t sb = (uint32_t)__cvta_generic_to_shared(smem);
    const int z = blockIdx.z;
    const __half* Ain = (z == 0) ? A0 : (z == 1) ? A1 : A2;
    const __half* Whi = Wb + (size_t)z * 2 * WN;
    const float* bias = (z == 0) ? b0 : (z == 1) ? b1 : b2;
    __nv_bfloat16* Chi = (z == 0) ? C0 : (z == 1) ? C1 : C2;
    const float scale = (z == 0) ? s0 : 1.0f;
    const bool useG = ((gmask >> z) & 1) != 0;

    const int nBase = blockIdx.x * 128;
    const int mBase = blockIdx.y * 256;
    int cnt = 0;
    if (useG) {
        cnt = counts[mBase >> 11];
        if ((mBase & 2047) >= cnt) return;
    }
    const int t = threadIdx.x;
    const int wid = t >> 5, lane = t & 31;
    const int wm = wid >> 1;
    const int wn = wid & 1;

    // A staging: row t>>1 (0..255), units (t&1)*4 + i (4 cp16/thread)
    const int sRow = t >> 1, uA = (t & 1) * 4;
    int srcRow;
    {
        int m = mBase + sRow;
        if (useG) {
            bool ok = (m & 2047) < cnt;
            srcRow = ok ? gather[m] : ((m >> 11) * SS);
        } else {
            srcRow = m;
        }
    }
    const __half* aHp = Ain + (size_t)srcRow * DD;
    // W staging: row t>>2 (0..127), units (t&3)*2 + i, both planes (4 cp16/thread)
    const int sRowW = t >> 2, uW = (t & 3) * 2;
    const __half* bHp = Whi + (size_t)(nBase + sRowW) * DD;

    const int g  = lane >> 3;
    const int lr = lane & 7;
    const uint32_t rowA = wm * 32 + (g & 1) * 8 + lr;
    const uint32_t rxa  = rowA & 7;
    const uint32_t aoff = rowA * 128;
    const int aU = g >> 1;
    const uint32_t rowB = wn * 64 + (g >> 1) * 8 + lr;
    const uint32_t rxb  = rowB & 7;
    const uint32_t boff = rowB * 128;
    const int bU = g & 1;

    float acc[2][8][4];
#pragma unroll
    for (int mt = 0; mt < 2; mt++)
#pragma unroll
        for (int j = 0; j < 8; j++)
#pragma unroll
            for (int r = 0; r < 4; r++) acc[mt][j][r] = 0.f;

    // smem layout per stage: A 0..32K, Wh 32K..48K, Wl 48K..64K
    auto stage = [&](int s, int k0) {
        const uint32_t bb = sb + s * GSTAGE2;
#pragma unroll
        for (int i = 0; i < 4; i++) {
            int u = uA + i;
            uint32_t sw = sRow * 128 + ((u ^ (sRow & 7)) << 4);
            cp16(bb + sw, aHp + k0 + u * 8);
        }
#pragma unroll
        for (int i = 0; i < 2; i++) {
            int u = uW + i;
            uint32_t sw = sRowW * 128 + ((u ^ (sRowW & 7)) << 4);
            cp16(bb + 32768 + sw, bHp + k0 + u * 8);
            cp16(bb + 49152 + sw, bHp + WN + k0 + u * 8);
        }
        cp_commit();
    };
    stage(0, 0);

    for (int c = 0; c < 16; c++) {
        cp_wait0();
        __syncthreads();
        if (c + 1 < 16) stage((c + 1) & 1, (c + 1) * 64);

        const uint32_t base = sb + (c & 1) * GSTAGE2;
#pragma unroll
        for (int ks = 0; ks < 4; ks++) {
            uint32_t ah[2][4];
#pragma unroll
            for (int mt = 0; mt < 2; mt++) {
                uint32_t sw = ((2 * ks + aU) ^ rxa) << 4;
                ldmx4(ah[mt], base + aoff + mt * 2048 + sw);
            }
#pragma unroll
            for (int jp = 0; jp < 4; jp++) {
                uint32_t sw = ((2 * ks + bU) ^ rxb) << 4;
                uint32_t rh[4], rl[4];
                ldmx4(rh, base + 32768 + boff + jp * 2048 + sw);
                ldmx4(rl, base + 49152 + boff + jp * 2048 + sw);
                mma_f16(acc[0][2 * jp],     ah[0], rh);
                mma_f16(acc[1][2 * jp],     ah[1], rh);
                mma_f16(acc[0][2 * jp + 1], ah[0], rh + 2);
                mma_f16(acc[1][2 * jp + 1], ah[1], rh + 2);
                mma_f16(acc[0][2 * jp],     ah[0], rl);
                mma_f16(acc[1][2 * jp],     ah[1], rl);
                mma_f16(acc[0][2 * jp + 1], ah[0], rl + 2);
                mma_f16(acc[1][2 * jp + 1], ah[1], rl + 2);
            }
        }
        __syncthreads();
    }

#pragma unroll
    for (int mt = 0; mt < 2; mt++) {
        int m0 = mBase + wm * 32 + mt * 16 + (lane >> 2);
        int m1 = m0 + 8;
        bool ok0 = true, ok1 = true;
        if (useG) {
            ok0 = (m0 & 2047) < cnt;
            ok1 = (m1 & 2047) < cnt;
        }
#pragma unroll
        for (int j = 0; j < 8; j++) {
            int n = nBase + wn * 64 + j * 8 + 2 * (lane & 3);
            float b0v = bias[n], b1v = bias[n + 1];
            float o00 = (acc[mt][j][0] + b0v) * scale;
            float o01 = (acc[mt][j][1] + b1v) * scale;
            float o10 = (acc[mt][j][2] + b0v) * scale;
            float o11 = (acc[mt][j][3] + b1v) * scale;
            if (Cf) {
                if (ok0) *(float2*)&Cf[(size_t)m0 * DD + n] = make_float2(o00, o01);
                if (ok1) *(float2*)&Cf[(size_t)m1 * DD + n] = make_float2(o10, o11);
            } else {
                if (ok0) {
                    __nv_bfloat16 h0 = __float2bfloat16(o00), h1 = __float2bfloat16(o01);
                    *(__nv_bfloat162*)&Chi[(size_t)m0 * DD + n] = __nv_bfloat162(h0, h1);
                    *(__nv_bfloat162*)&Chi[ACT + (size_t)m0 * DD + n] = __nv_bfloat162(
                        __float2bfloat16(o00 - __bfloat162float(h0)),
                        __float2bfloat16(o01 - __bfloat162float(h1)));
                }
                if (ok1) {
                    __nv_bfloat16 h0 = __float2bfloat16(o10), h1 = __float2bfloat16(o11);
                    *(__nv_bfloat162*)&Chi[(size_t)m1 * DD + n] = __nv_bfloat162(h0, h1);
                    *(__nv_bfloat162*)&Chi[ACT + (size_t)m1 * DD + n] = __nv_bfloat162(
                        __float2bfloat16(o10 - __bfloat162float(h0)),
                        __float2bfloat16(o11 - __bfloat162float(h1)));
                }
            }
        }
    }
}

// ---------------------------------------------------------------------------
// Kernel 3: tensor-core flash attention (bf16 hi/lo, unchanged math;
// epilogue now writes a single fp16 plane for the O projection)
// ---------------------------------------------------------------------------
#define ASM_KH 0
#define ASM_KL 16384
#define ASM_VH 32768
#define ASM_VL 49152
#define ATTN_SMEM 65536

__global__ __launch_bounds__(256, 2) void attn_mma_kernel(
    const __nv_bfloat16* __restrict__ Qh_, const __nv_bfloat16* __restrict__ Ql_,
    const __nv_bfloat16* __restrict__ Kh_, const __nv_bfloat16* __restrict__ Kl_,
    const __nv_bfloat16* __restrict__ Vh_, const __nv_bfloat16* __restrict__ Vl_,
    __half* __restrict__ O_,
    const int* __restrict__ counts)
{
    extern __shared__ char smem[];
    const uint32_t sb = (uint32_t)__cvta_generic_to_shared(smem);
    const int qb = blockIdx.x, h = blockIdx.y, b = blockIdx.z;
    const int t = threadIdx.x, w = t >> 5, lane = t & 31;
    const int q0 = qb * 128;
    const int cnt = counts[b];
    const int nb = (cnt + 63) >> 6;
    const size_t hoff = (size_t)h * HDIM;

    const int g  = lane >> 3;
    const int lr = lane & 7;
    const uint32_t rowA = w * 16 + (g & 1) * 8 + lr;
    const uint32_t rxa  = rowA & 7;
    const uint32_t aoff = rowA * 128;
    const int aU = g >> 1;
    const uint32_t rowB = (g >> 1) * 8 + lr;
    const uint32_t rxb  = rowB & 7;
    const int bU = g & 1;
    const uint32_t rowV = (g & 1) * 8 + lr;
    const uint32_t rxv  = rowV & 7;
    const int vU = g >> 1;

    {
        const int sRowQ = t >> 1, uBQ = (t & 1) * 4;
        const __nv_bfloat16* qhp = Qh_ + (size_t)(b * SS + q0 + sRowQ) * DD + hoff;
        const __nv_bfloat16* qlp = Ql_ + (size_t)(b * SS + q0 + sRowQ) * DD + hoff;
#pragma unroll
        for (int i = 0; i < 4; i++) {
            int u = uBQ + i;
            uint32_t off = sRowQ * 128 + ((u ^ (sRowQ & 7)) << 4);
            cp16(sb + off,         qhp + u * 8);
            cp16(sb + 16384 + off, qlp + u * 8);
        }
        cp_commit();
    }
    cp_wait0();
    __syncthreads();

    uint32_t qah[4][4], qal[4][4];
#pragma unroll
    for (int ks = 0; ks < 4; ks++) {
        const uint32_t swA = ((2 * ks + aU) ^ rxa) << 4;
        ldmx4(qah[ks], sb +         aoff + swA);
        ldmx4(qal[ks], sb + 16384 + aoff + swA);
    }
    __syncthreads();

    const int sRowK = t >> 2, uBK = (t & 3) * 2;
    auto stage_kv = [&](int bufI, int kbase) {
        const size_t rb = (size_t)(b * SS + kbase + sRowK) * DD + hoff;
        const uint32_t o = bufI * 8192;
#pragma unroll
        for (int i = 0; i < 2; i++) {
            int u = uBK + i;
            uint32_t sw = sRowK * 128 + ((u ^ (sRowK & 7)) << 4);
            cp16(sb + ASM_KH + o + sw, Kh_ + rb + u * 8);
            cp16(sb + ASM_KL + o + sw, Kl_ + rb + u * 8);
            cp16(sb + ASM_VH + o + sw, Vh_ + rb + u * 8);
            cp16(sb + ASM_VL + o + sw, Vl_ + rb + u * 8);
        }
    };
    stage_kv(0, 0);
    cp_commit();

    float m0 = -1e30f, m1 = -1e30f, l0 = 0.f, l1 = 0.f;
    float oacc[8][4];
#pragma unroll
    for (int j = 0; j < 8; j++)
#pragma unroll
        for (int r = 0; r < 4; r++) oacc[j][r] = 0.f;

    int buf = 0;
    for (int kb = 0; kb < nb; kb++) {
        cp_wait0();
        __syncthreads();
        if (kb + 1 < nb) {
            stage_kv(buf ^ 1, (kb + 1) * 64);
            cp_commit();
        }

        const uint32_t tKH = sb + ASM_KH + buf * 8192;
        const uint32_t tKL = sb + ASM_KL + buf * 8192;

        float sacc[8][4];
#pragma unroll
        for (int j = 0; j < 8; j++)
#pragma unroll
            for (int r = 0; r < 4; r++) sacc[j][r] = 0.f;
#pragma unroll
        for (int ks = 0; ks < 4; ks++) {
#pragma unroll
            for (int jp = 0; jp < 4; jp++) {
                const uint32_t addr = (rowB + 16 * jp) * 128 + (((2 * ks + bU) ^ rxb) << 4);
                uint32_t rh[4], rl[4];
                ldmx4(rh, tKH + addr);
                ldmx4(rl, tKL + addr);
                mma_bf16(sacc[2 * jp],     qah[ks], rh);
                mma_bf16(sacc[2 * jp + 1], qah[ks], rh + 2);
                mma_bf16(sacc[2 * jp],     qah[ks], rl);
                mma_bf16(sacc[2 * jp + 1], qah[ks], rl + 2);
                mma_bf16(sacc[2 * jp],     qal[ks], rh);
                mma_bf16(sacc[2 * jp + 1], qal[ks], rh + 2);
            }
        }

        const int kcol = kb * 64 + 2 * (lane & 3);
#pragma unroll
        for (int j = 0; j < 8; j++) {
            const int kc = kcol + 8 * j;
            if (kc >= cnt)     { sacc[j][0] = -1e30f; sacc[j][2] = -1e30f; }
            if (kc + 1 >= cnt) { sacc[j][1] = -1e30f; sacc[j][3] = -1e30f; }
        }

        float rm0 = -1e30f, rm1 = -1e30f;
#pragma unroll
        for (int j = 0; j < 8; j++) {
            rm0 = fmaxf(rm0, fmaxf(sacc[j][0], sacc[j][1]));
            rm1 = fmaxf(rm1, fmaxf(sacc[j][2], sacc[j][3]));
        }
        rm0 = fmaxf(rm0, __shfl_xor_sync(0xffffffffu, rm0, 1));
        rm0 = fmaxf(rm0, __shfl_xor_sync(0xffffffffu, rm0, 2));
        rm1 = fmaxf(rm1, __shfl_xor_sync(0xffffffffu, rm1, 1));
        rm1 = fmaxf(rm1, __shfl_xor_sync(0xffffffffu, rm1, 2));
        const float nm0 = fmaxf(m0, rm0), nm1 = fmaxf(m1, rm1);
        const float c0 = ex2(m0 - nm0), c1 = ex2(m1 - nm1);
        m0 = nm0; m1 = nm1;
        float rs0 = 0.f, rs1 = 0.f;
#pragma unroll
        for (int j = 0; j < 8; j++) {
            sacc[j][0] = ex2(sacc[j][0] - nm0);
            sacc[j][1] = ex2(sacc[j][1] - nm0);
            sacc[j][2] = ex2(sacc[j][2] - nm1);
            sacc[j][3] = ex2(sacc[j][3] - nm1);
            rs0 += sacc[j][0] + sacc[j][1];
            rs1 += sacc[j][2] + sacc[j][3];
        }
        rs0 += __shfl_xor_sync(0xffffffffu, rs0, 1);
        rs0 += __shfl_xor_sync(0xffffffffu, rs0, 2);
        rs1 += __shfl_xor_sync(0xffffffffu, rs1, 1);
        rs1 += __shfl_xor_sync(0xffffffffu, rs1, 2);
        l0 = l0 * c0 + rs0;
        l1 = l1 * c1 + rs1;
#pragma unroll
        for (int j = 0; j < 8; j++) {
            oacc[j][0] *= c0; oacc[j][1] *= c0;
            oacc[j][2] *= c1; oacc[j][3] *= c1;
        }

        const uint32_t tVH = sb + ASM_VH + buf * 8192;
        const uint32_t tVL = sb + ASM_VL + buf * 8192;
#pragma unroll
        for (int ks = 0; ks < 4; ks++) {
            const int nt0 = 2 * ks, nt1 = 2 * ks + 1;
            uint32_t aPh[4], aPl[4];
            {
                float p00 = sacc[nt0][0], p01 = sacc[nt0][1];
                float p02 = sacc[nt0][2], p03 = sacc[nt0][3];
                float p10 = sacc[nt1][0], p11 = sacc[nt1][1];
                float p12 = sacc[nt1][2], p13 = sacc[nt1][3];
                __nv_bfloat16 h00 = __float2bfloat16(p00), h01 = __float2bfloat16(p01);
                __nv_bfloat16 h02 = __float2bfloat16(p02), h03 = __float2bfloat16(p03);
                __nv_bfloat16 h10 = __float2bfloat16(p10), h11 = __float2bfloat16(p11);
                __nv_bfloat16 h12 = __float2bfloat16(p12), h13 = __float2bfloat16(p13);
                __nv_bfloat162 v0(h00, h01), v1(h02, h03), v2(h10, h11), v3(h12, h13);
                aPh[0] = *(uint32_t*)&v0; aPh[1] = *(uint32_t*)&v1;
                aPh[2] = *(uint32_t*)&v2; aPh[3] = *(uint32_t*)&v3;
                aPl[0] = pack_bf16(p00 - __bfloat162float(h00), p01 - __bfloat162float(h01));
                aPl[1] = pack_bf16(p02 - __bfloat162float(h02), p03 - __bfloat162float(h03));
                aPl[2] = pack_bf16(p10 - __bfloat162float(h10), p11 - __bfloat162float(h11));
                aPl[3] = pack_bf16(p12 - __bfloat162float(h12), p13 - __bfloat162float(h13));
            }
#pragma unroll
            for (int dp = 0; dp < 4; dp++) {
                const uint32_t addr = (rowV + 16 * ks) * 128 + (((2 * dp + vU) ^ rxv) << 4);
                uint32_t rvh[4], rvl[4];
                ldmx4t(rvh, tVH + addr);
                ldmx4t(rvl, tVL + addr);
                mma_bf16(oacc[2 * dp],     aPh, rvh);
                mma_bf16(oacc[2 * dp + 1], aPh, rvh + 2);
                mma_bf16(oacc[2 * dp],     aPh, rvl);
                mma_bf16(oacc[2 * dp + 1], aPh, rvl + 2);
                mma_bf16(oacc[2 * dp],     aPl, rvh);
                mma_bf16(oacc[2 * dp + 1], aPl, rvh + 2);
            }
        }
        buf ^= 1;
    }

    const float inv0 = 1.0f / l0, inv1 = 1.0f / l1;
    const int row0 = b * SS + q0 + w * 16 + (lane >> 2);
    const int row1 = row0 + 8;
    const int dbase = h * HDIM + 2 * (lane & 3);
#pragma unroll
    for (int j = 0; j < 8; j++) {
        size_t a0 = (size_t)row0 * DD + dbase + 8 * j;
        size_t a1 = (size_t)row1 * DD + dbase + 8 * j;
        __half2 o0 = __floats2half2_rn(oacc[j][0] * inv0, oacc[j][1] * inv0);
        __half2 o1 = __floats2half2_rn(oacc[j][2] * inv1, oacc[j][3] * inv1);
        *(__half2*)&O_[a0] = o0;
        *(__half2*)&O_[a1] = o1;
    }
}

// ---------------------------------------------------------------------------
// Launch
// ---------------------------------------------------------------------------
extern "C" void kernel_launch(void* const* d_in, const int* in_sizes, int n_in,
                              void* d_out, int out_size)
{
    (void)out_size;
    const float* qkv[3]   = {nullptr, nullptr, nullptr};
    const int*   masks[2] = {nullptr, nullptr};
    const float* Ws[4]    = {nullptr, nullptr, nullptr, nullptr};
    const float* bs[4]    = {nullptr, nullptr, nullptr, nullptr};
    int nqkv = 0, nmask = 0, nW = 0, nb = 0;
    for (int i = 0; i < n_in; i++) {
        int sz = in_sizes[i];
        if (sz == MTOT * DD && nqkv < 3)      qkv[nqkv++] = (const float*)d_in[i];
        else if (sz == MTOT && nmask < 2)     masks[nmask++] = (const int*)d_in[i];
        else if (sz == DD * DD && nW < 4)     Ws[nW++] = (const float*)d_in[i];
        else if (sz == DD && nb < 4)          bs[nb++] = (const float*)d_in[i];
    }

    static int attr_done = 0;
    if (!attr_done) {
        cudaFuncSetAttribute(gemm_mma_kernel,
                             cudaFuncAttributeMaxDynamicSharedMemorySize, GSM2_BYTES);
        cudaFuncSetAttribute(attn_mma_kernel,
                             cudaFuncAttributeMaxDynamicSharedMemorySize, ATTN_SMEM);
        attr_done = 1;
    }

    int *gidx, *gcnt;
    __half *gq, *gk, *gv, *gW, *ga;
    __nv_bfloat16 *gpq, *gpk, *gpv;
    cudaGetSymbolAddress((void**)&gidx, g_idx);
    cudaGetSymbolAddress((void**)&gcnt, g_cnt);
    cudaGetSymbolAddress((void**)&gq, g_q);
    cudaGetSymbolAddress((void**)&gk, g_k);
    cudaGetSymbolAddress((void**)&gv, g_v);
    cudaGetSymbolAddress((void**)&gW, g_W);
    cudaGetSymbolAddress((void**)&gpq, g_pq);
    cudaGetSymbolAddress((void**)&gpk, g_pk);
    cudaGetSymbolAddress((void**)&gpv, g_pv);
    cudaGetSymbolAddress((void**)&ga, g_a);

    const int N8_ACT = (int)(ACT / 8);
    const int N8_W   = (int)(WN / 8);

    build_idx_kernel<<<BB, 1024>>>(masks[0], masks[1], gidx, gcnt);

    {
        ConvHArgs aa = {};
        aa.src[0] = qkv[0]; aa.dst[0] = gq;
        aa.src[1] = qkv[1]; aa.dst[1] = gk;
        aa.src[2] = qkv[2]; aa.dst[2] = gv;
        conv_half_multi<<<dim3((N8_ACT + 255) / 256, 3), 256>>>(aa, N8_ACT);

        ConvWArgs wa = {};
        for (int w = 0; w < 4; w++) {
            wa.src[w] = Ws[w];
            wa.hi[w]  = gW + (size_t)w * 2 * WN;
            wa.lo[w]  = gW + (size_t)w * 2 * WN + WN;
        }
        conv_wsplit_multi<<<dim3((N8_W + 255) / 256, 4), 256>>>(wa, N8_W);
    }

    const float QSCALE = 0.125f * 1.4426950408889634f;
    gemm_mma_kernel<<<dim3(DD / 128, MTOT / 256, 3), 512, GSM2_BYTES>>>(
        gq, gk, gv, gW, bs[0], bs[1], bs[2], QSCALE,
        nullptr, gpq, gpk, gpv, gidx, gcnt, 0b110);

    attn_mma_kernel<<<dim3(SS / 128, HH, BB), 256, ATTN_SMEM>>>(
        gpq, gpq + ACT, gpk, gpk + ACT, gpv, gpv + ACT, ga, gcnt);

    gemm_mma_kernel<<<dim3(DD / 128, MTOT / 256, 1), 512, GSM2_BYTES>>>(
        ga, ga, ga, gW + (size_t)3 * 2 * WN, bs[3], bs[3], bs[3], 1.0f,
        (float*)d_out, nullptr, nullptr, nullptr, nullptr, nullptr, 0);
}

// round 15
// speedup vs baseline: 1.5306x; 1.2076x over previous
#include <cuda_runtime.h>
#include <cuda_bf16.h>
#include <cuda_fp16.h>
#include <cstdint>
#include <cstddef>

// Problem constants
#define BB 2
#define SS 2048
#define DD 1024
#define HH 16
#define HDIM 64
#define MTOT (BB * SS) // 4096

#define ACT ((size_t)MTOT * DD)  // 4194304 elements
#define WN  ((size_t)DD * DD)    // 1048576 elements

// ---------------------------------------------------------------------------
// Scratch (device globals)
// ---------------------------------------------------------------------------
__device__ int g_idx[MTOT];
__device__ int g_cnt[BB];
__device__ __half g_q[MTOT * DD];          // fp16 activations
__device__ __half g_k[MTOT * DD];
__device__ __half g_v[MTOT * DD];
__device__ __half g_W[4][2 * DD * DD];     // fp16 hi/lo weights (lo at +WN)
__device__ __half g_pq[MTOT * DD];         // projected Q/K/V, fp16 single-plane
__device__ __half g_pk[MTOT * DD];
__device__ __half g_pv[MTOT * DD];
__device__ __half g_a[MTOT * DD];          // attention output, fp16

// ---------------------------------------------------------------------------
// PTX helpers
// ---------------------------------------------------------------------------
__device__ __forceinline__ void cp16(unsigned dst, const void* src) {
    asm volatile("cp.async.cg.shared.global [%0], [%1], 16;" :: "r"(dst), "l"(src));
}
__device__ __forceinline__ void cp_commit() { asm volatile("cp.async.commit_group;"); }
__device__ __forceinline__ void cp_wait0()  { asm volatile("cp.async.wait_group 0;" ::: "memory"); }

__device__ __forceinline__ void ldmx4(uint32_t* r, uint32_t addr) {
    asm volatile("ldmatrix.sync.aligned.m8n8.x4.shared.b16 {%0,%1,%2,%3}, [%4];"
                 : "=r"(r[0]), "=r"(r[1]), "=r"(r[2]), "=r"(r[3]) : "r"(addr));
}
__device__ __forceinline__ void ldmx4t(uint32_t* r, uint32_t addr) {
    asm volatile("ldmatrix.sync.aligned.m8n8.x4.trans.shared.b16 {%0,%1,%2,%3}, [%4];"
                 : "=r"(r[0]), "=r"(r[1]), "=r"(r[2]), "=r"(r[3]) : "r"(addr));
}
__device__ __forceinline__ void mma_f16(float* d, const uint32_t* a, const uint32_t* b) {
    asm volatile(
        "mma.sync.aligned.m16n8k16.row.col.f32.f16.f16.f32 "
        "{%0,%1,%2,%3}, {%4,%5,%6,%7}, {%8,%9}, {%0,%1,%2,%3};"
        : "+f"(d[0]), "+f"(d[1]), "+f"(d[2]), "+f"(d[3])
        : "r"(a[0]), "r"(a[1]), "r"(a[2]), "r"(a[3]), "r"(b[0]), "r"(b[1]));
}
__device__ __forceinline__ float ex2(float x) {
    float r;
    asm("ex2.approx.f32 %0, %1;" : "=f"(r) : "f"(x));
    return r;
}

// ---------------------------------------------------------------------------
// Conv kernels: fp32 -> fp16 single (activations), fp32 -> fp16 hi/lo (weights)
// ---------------------------------------------------------------------------
struct ConvHArgs {
    const float* src[4];
    __half* dst[4];
};
__global__ __launch_bounds__(256) void conv_half_multi(ConvHArgs a, int n8)
{
    int i = blockIdx.x * blockDim.x + threadIdx.x;
    if (i >= n8) return;
    const int y = blockIdx.y;
    const float* x = a.src[y];
    float4 v0 = ((const float4*)x)[2 * i];
    float4 v1 = ((const float4*)x)[2 * i + 1];
    __half2 h0 = __floats2half2_rn(v0.x, v0.y);
    __half2 h1 = __floats2half2_rn(v0.z, v0.w);
    __half2 h2 = __floats2half2_rn(v1.x, v1.y);
    __half2 h3 = __floats2half2_rn(v1.z, v1.w);
    ((uint4*)a.dst[y])[i] = make_uint4(*(uint32_t*)&h0, *(uint32_t*)&h1,
                                       *(uint32_t*)&h2, *(uint32_t*)&h3);
}

struct ConvWArgs {
    const float* src[4];
    __half* hi[4];
    __half* lo[4];
};
__global__ __launch_bounds__(256) void conv_wsplit_multi(ConvWArgs a, int n8)
{
    int i = blockIdx.x * blockDim.x + threadIdx.x;
    if (i >= n8) return;
    const int y = blockIdx.y;
    const float* x = a.src[y];
    float4 v0 = ((const float4*)x)[2 * i];
    float4 v1 = ((const float4*)x)[2 * i + 1];
    float f[8] = {v0.x, v0.y, v0.z, v0.w, v1.x, v1.y, v1.z, v1.w};
    uint32_t hp[4], lp[4];
#pragma unroll
    for (int j = 0; j < 4; j++) {
        __half h0 = __float2half_rn(f[2 * j]);
        __half h1 = __float2half_rn(f[2 * j + 1]);
        __half l0 = __float2half_rn(f[2 * j] - __half2float(h0));
        __half l1 = __float2half_rn(f[2 * j + 1] - __half2float(h1));
        __half2 hv(h0, h1), lv(l0, l1);
        hp[j] = *(uint32_t*)&hv;
        lp[j] = *(uint32_t*)&lv;
    }
    ((uint4*)a.hi[y])[i] = make_uint4(hp[0], hp[1], hp[2], hp[3]);
    ((uint4*)a.lo[y])[i] = make_uint4(lp[0], lp[1], lp[2], lp[3]);
}

// ---------------------------------------------------------------------------
// Kernel 1: deterministic mask compaction
// ---------------------------------------------------------------------------
__global__ __launch_bounds__(1024) void build_idx_kernel(
    const int* __restrict__ kp, const int* __restrict__ am,
    int* __restrict__ idx, int* __restrict__ counts)
{
    __shared__ int ssum[1024];
    const int b = blockIdx.x;
    const int t = threadIdx.x;
    const int base = b * SS;
    const int s0 = 2 * t, s1 = 2 * t + 1;
    int v0 = (kp[base + s0] == 0 && am[base + s0] == 0) ? 1 : 0;
    int v1 = (kp[base + s1] == 0 && am[base + s1] == 0) ? 1 : 0;
    ssum[t] = v0 + v1;
    __syncthreads();
    for (int off = 1; off < 1024; off <<= 1) {
        int add = (t >= off) ? ssum[t - off] : 0;
        int val = ssum[t];
        __syncthreads();
        ssum[t] = val + add;
        __syncthreads();
    }
    int excl = ssum[t] - (v0 + v1);
    if (v0) idx[base + excl]      = base + s0;
    if (v1) idx[base + excl + v0] = base + s1;
    if (t == 1023) counts[b] = ssum[1023];
}

// ---------------------------------------------------------------------------
// Kernel 2: f16 HMMA GEMM, tile 256x128, BK=64, 512 threads.
// A = plain fp16, W = fp16 hi/lo: C = A*Wh + A*Wl (fp32 accum).
// Output: fp32 (Cf) or fp16 single-plane (Ch).
// ---------------------------------------------------------------------------
#define GSTAGE2 65536
#define GSM2_BYTES (2 * GSTAGE2)

__global__ __launch_bounds__(512, 1) void gemm_mma_kernel(
    const __half* __restrict__ A0, const __half* __restrict__ A1,
    const __half* __restrict__ A2,
    const __half* __restrict__ Wb,          // weight z at Wb + z*2*WN; lo at +WN
    const float* __restrict__ b0, const float* __restrict__ b1,
    const float* __restrict__ b2,
    float s0,
    float* __restrict__ Cf,
    __half* __restrict__ C0, __half* __restrict__ C1, __half* __restrict__ C2,
    const int* __restrict__ gather, const int* __restrict__ counts, int gmask)
{
    extern __shared__ char smem[];
    const uint32_t sb = (uint32_t)__cvta_generic_to_shared(smem);
    const int z = blockIdx.z;
    const __half* Ain = (z == 0) ? A0 : (z == 1) ? A1 : A2;
    const __half* Whi = Wb + (size_t)z * 2 * WN;
    const float* bias = (z == 0) ? b0 : (z == 1) ? b1 : b2;
    __half* Ch = (z == 0) ? C0 : (z == 1) ? C1 : C2;
    const float scale = (z == 0) ? s0 : 1.0f;
    const bool useG = ((gmask >> z) & 1) != 0;

    const int nBase = blockIdx.x * 128;
    const int mBase = blockIdx.y * 256;
    int cnt = 0;
    if (useG) {
        cnt = counts[mBase >> 11];
        if ((mBase & 2047) >= cnt) return;
    }
    const int t = threadIdx.x;
    const int wid = t >> 5, lane = t & 31;
    const int wm = wid >> 1;
    const int wn = wid & 1;

    const int sRow = t >> 1, uA = (t & 1) * 4;
    int srcRow;
    {
        int m = mBase + sRow;
        if (useG) {
            bool ok = (m & 2047) < cnt;
            srcRow = ok ? gather[m] : ((m >> 11) * SS);
        } else {
            srcRow = m;
        }
    }
    const __half* aHp = Ain + (size_t)srcRow * DD;
    const int sRowW = t >> 2, uW = (t & 3) * 2;
    const __half* bHp = Whi + (size_t)(nBase + sRowW) * DD;

    const int g  = lane >> 3;
    const int lr = lane & 7;
    const uint32_t rowA = wm * 32 + (g & 1) * 8 + lr;
    const uint32_t rxa  = rowA & 7;
    const uint32_t aoff = rowA * 128;
    const int aU = g >> 1;
    const uint32_t rowB = wn * 64 + (g >> 1) * 8 + lr;
    const uint32_t rxb  = rowB & 7;
    const uint32_t boff = rowB * 128;
    const int bU = g & 1;

    float acc[2][8][4];
#pragma unroll
    for (int mt = 0; mt < 2; mt++)
#pragma unroll
        for (int j = 0; j < 8; j++)
#pragma unroll
            for (int r = 0; r < 4; r++) acc[mt][j][r] = 0.f;

    // smem layout per stage: A 0..32K, Wh 32K..48K, Wl 48K..64K
    auto stage = [&](int s, int k0) {
        const uint32_t bb = sb + s * GSTAGE2;
#pragma unroll
        for (int i = 0; i < 4; i++) {
            int u = uA + i;
            uint32_t sw = sRow * 128 + ((u ^ (sRow & 7)) << 4);
            cp16(bb + sw, aHp + k0 + u * 8);
        }
#pragma unroll
        for (int i = 0; i < 2; i++) {
            int u = uW + i;
            uint32_t sw = sRowW * 128 + ((u ^ (sRowW & 7)) << 4);
            cp16(bb + 32768 + sw, bHp + k0 + u * 8);
            cp16(bb + 49152 + sw, bHp + WN + k0 + u * 8);
        }
        cp_commit();
    };
    stage(0, 0);

    for (int c = 0; c < 16; c++) {
        cp_wait0();
        __syncthreads();
        if (c + 1 < 16) stage((c + 1) & 1, (c + 1) * 64);

        const uint32_t base = sb + (c & 1) * GSTAGE2;
#pragma unroll
        for (int ks = 0; ks < 4; ks++) {
            uint32_t ah[2][4];
#pragma unroll
            for (int mt = 0; mt < 2; mt++) {
                uint32_t sw = ((2 * ks + aU) ^ rxa) << 4;
                ldmx4(ah[mt], base + aoff + mt * 2048 + sw);
            }
#pragma unroll
            for (int jp = 0; jp < 4; jp++) {
                uint32_t sw = ((2 * ks + bU) ^ rxb) << 4;
                uint32_t rh[4], rl[4];
                ldmx4(rh, base + 32768 + boff + jp * 2048 + sw);
                ldmx4(rl, base + 49152 + boff + jp * 2048 + sw);
                mma_f16(acc[0][2 * jp],     ah[0], rh);
                mma_f16(acc[1][2 * jp],     ah[1], rh);
                mma_f16(acc[0][2 * jp + 1], ah[0], rh + 2);
                mma_f16(acc[1][2 * jp + 1], ah[1], rh + 2);
                mma_f16(acc[0][2 * jp],     ah[0], rl);
                mma_f16(acc[1][2 * jp],     ah[1], rl);
                mma_f16(acc[0][2 * jp + 1], ah[0], rl + 2);
                mma_f16(acc[1][2 * jp + 1], ah[1], rl + 2);
            }
        }
        __syncthreads();
    }

#pragma unroll
    for (int mt = 0; mt < 2; mt++) {
        int m0 = mBase + wm * 32 + mt * 16 + (lane >> 2);
        int m1 = m0 + 8;
        bool ok0 = true, ok1 = true;
        if (useG) {
            ok0 = (m0 & 2047) < cnt;
            ok1 = (m1 & 2047) < cnt;
        }
#pragma unroll
        for (int j = 0; j < 8; j++) {
            int n = nBase + wn * 64 + j * 8 + 2 * (lane & 3);
            float b0v = bias[n], b1v = bias[n + 1];
            float o00 = (acc[mt][j][0] + b0v) * scale;
            float o01 = (acc[mt][j][1] + b1v) * scale;
            float o10 = (acc[mt][j][2] + b0v) * scale;
            float o11 = (acc[mt][j][3] + b1v) * scale;
            if (Cf) {
                if (ok0) *(float2*)&Cf[(size_t)m0 * DD + n] = make_float2(o00, o01);
                if (ok1) *(float2*)&Cf[(size_t)m1 * DD + n] = make_float2(o10, o11);
            } else {
                if (ok0) *(__half2*)&Ch[(size_t)m0 * DD + n] = __floats2half2_rn(o00, o01);
                if (ok1) *(__half2*)&Ch[(size_t)m1 * DD + n] = __floats2half2_rn(o10, o11);
            }
        }
    }
}

// ---------------------------------------------------------------------------
// Kernel 3: tensor-core flash attention — fp16 single-plane Q/K/V/P.
// CTA: 128 q-rows, 8 warps. 64-key k-blocks, K/V double-buffered.
// Smem 32KB: K[2] 0..16K | V[2] 16K..32K (Q staged in 0..16K during prologue).
// ---------------------------------------------------------------------------
#define ASM_K 0
#define ASM_V 16384
#define ATTN_SMEM 32768

__global__ __launch_bounds__(256, 2) void attn_mma_kernel(
    const __half* __restrict__ Q_, const __half* __restrict__ K_,
    const __half* __restrict__ V_, __half* __restrict__ O_,
    const int* __restrict__ counts)
{
    extern __shared__ char smem[];
    const uint32_t sb = (uint32_t)__cvta_generic_to_shared(smem);
    const int qb = blockIdx.x, h = blockIdx.y, b = blockIdx.z;
    const int t = threadIdx.x, w = t >> 5, lane = t & 31;
    const int q0 = qb * 128;
    const int cnt = counts[b];
    const int nb = (cnt + 63) >> 6;
    const size_t hoff = (size_t)h * HDIM;

    const int g  = lane >> 3;
    const int lr = lane & 7;
    const uint32_t rowA = w * 16 + (g & 1) * 8 + lr;
    const uint32_t rxa  = rowA & 7;
    const uint32_t aoff = rowA * 128;
    const int aU = g >> 1;
    const uint32_t rowB = (g >> 1) * 8 + lr;
    const uint32_t rxb  = rowB & 7;
    const int bU = g & 1;
    const uint32_t rowV = (g & 1) * 8 + lr;
    const uint32_t rxv  = rowV & 7;
    const int vU = g >> 1;

    // ---- prologue: stage Q plane (16KB) into smem 0..16K
    {
        const int sRowQ = t >> 1, uBQ = (t & 1) * 4;
        const __half* qp = Q_ + (size_t)(b * SS + q0 + sRowQ) * DD + hoff;
#pragma unroll
        for (int i = 0; i < 4; i++) {
            int u = uBQ + i;
            uint32_t off = sRowQ * 128 + ((u ^ (sRowQ & 7)) << 4);
            cp16(sb + off, qp + u * 8);
        }
        cp_commit();
    }
    cp_wait0();
    __syncthreads();

    uint32_t qa[4][4];
#pragma unroll
    for (int ks = 0; ks < 4; ks++) {
        const uint32_t swA = ((2 * ks + aU) ^ rxa) << 4;
        ldmx4(qa[ks], sb + aoff + swA);
    }
    __syncthreads(); // Q consumed; smem becomes K/V buffers

    // K/V staging: 64 rows x 8 units per tile; 2 units/thread
    const int sRowK = t >> 2, uBK = (t & 3) * 2;
    auto stage_kv = [&](int bufI, int kbase) {
        const size_t rb = (size_t)(b * SS + kbase + sRowK) * DD + hoff;
        const uint32_t o = bufI * 8192;
#pragma unroll
        for (int i = 0; i < 2; i++) {
            int u = uBK + i;
            uint32_t sw = sRowK * 128 + ((u ^ (sRowK & 7)) << 4);
            cp16(sb + ASM_K + o + sw, K_ + rb + u * 8);
            cp16(sb + ASM_V + o + sw, V_ + rb + u * 8);
        }
    };
    stage_kv(0, 0);
    cp_commit();

    float m0 = -1e30f, m1 = -1e30f, l0 = 0.f, l1 = 0.f;
    float oacc[8][4];
#pragma unroll
    for (int j = 0; j < 8; j++)
#pragma unroll
        for (int r = 0; r < 4; r++) oacc[j][r] = 0.f;

    int buf = 0;
    for (int kb = 0; kb < nb; kb++) {
        cp_wait0();
        __syncthreads();
        if (kb + 1 < nb) {
            stage_kv(buf ^ 1, (kb + 1) * 64);
            cp_commit();
        }

        const uint32_t tK = sb + ASM_K + buf * 8192;

        // ---- S = Q K^T (single product)
        float sacc[8][4];
#pragma unroll
        for (int j = 0; j < 8; j++)
#pragma unroll
            for (int r = 0; r < 4; r++) sacc[j][r] = 0.f;
#pragma unroll
        for (int ks = 0; ks < 4; ks++) {
#pragma unroll
            for (int jp = 0; jp < 4; jp++) {
                const uint32_t addr = (rowB + 16 * jp) * 128 + (((2 * ks + bU) ^ rxb) << 4);
                uint32_t rh[4];
                ldmx4(rh, tK + addr);
                mma_f16(sacc[2 * jp],     qa[ks], rh);
                mma_f16(sacc[2 * jp + 1], qa[ks], rh + 2);
            }
        }

        // ---- mask tail keys
        const int kcol = kb * 64 + 2 * (lane & 3);
#pragma unroll
        for (int j = 0; j < 8; j++) {
            const int kc = kcol + 8 * j;
            if (kc >= cnt)     { sacc[j][0] = -1e30f; sacc[j][2] = -1e30f; }
            if (kc + 1 >= cnt) { sacc[j][1] = -1e30f; sacc[j][3] = -1e30f; }
        }

        // ---- online softmax (base-2; Q pre-scaled by 0.125*log2e)
        float rm0 = -1e30f, rm1 = -1e30f;
#pragma unroll
        for (int j = 0; j < 8; j++) {
            rm0 = fmaxf(rm0, fmaxf(sacc[j][0], sacc[j][1]));
            rm1 = fmaxf(rm1, fmaxf(sacc[j][2], sacc[j][3]));
        }
        rm0 = fmaxf(rm0, __shfl_xor_sync(0xffffffffu, rm0, 1));
        rm0 = fmaxf(rm0, __shfl_xor_sync(0xffffffffu, rm0, 2));
        rm1 = fmaxf(rm1, __shfl_xor_sync(0xffffffffu, rm1, 1));
        rm1 = fmaxf(rm1, __shfl_xor_sync(0xffffffffu, rm1, 2));
        const float nm0 = fmaxf(m0, rm0), nm1 = fmaxf(m1, rm1);
        const float c0 = ex2(m0 - nm0), c1 = ex2(m1 - nm1);
        m0 = nm0; m1 = nm1;
        float rs0 = 0.f, rs1 = 0.f;
#pragma unroll
        for (int j = 0; j < 8; j++) {
            sacc[j][0] = ex2(sacc[j][0] - nm0);
            sacc[j][1] = ex2(sacc[j][1] - nm0);
            sacc[j][2] = ex2(sacc[j][2] - nm1);
            sacc[j][3] = ex2(sacc[j][3] - nm1);
            rs0 += sacc[j][0] + sacc[j][1];
            rs1 += sacc[j][2] + sacc[j][3];
        }
        rs0 += __shfl_xor_sync(0xffffffffu, rs0, 1);
        rs0 += __shfl_xor_sync(0xffffffffu, rs0, 2);
        rs1 += __shfl_xor_sync(0xffffffffu, rs1, 1);
        rs1 += __shfl_xor_sync(0xffffffffu, rs1, 2);
        l0 = l0 * c0 + rs0;
        l1 = l1 * c1 + rs1;
#pragma unroll
        for (int j = 0; j < 8; j++) {
            oacc[j][0] *= c0; oacc[j][1] *= c0;
            oacc[j][2] *= c1; oacc[j][3] *= c1;
        }

        // ---- O += P V (fp16 P, single product)
        const uint32_t tV = sb + ASM_V + buf * 8192;
#pragma unroll
        for (int ks = 0; ks < 4; ks++) {
            const int nt0 = 2 * ks, nt1 = 2 * ks + 1;
            uint32_t aP[4];
            {
                __half2 p0 = __floats2half2_rn(sacc[nt0][0], sacc[nt0][1]);
                __half2 p1 = __floats2half2_rn(sacc[nt0][2], sacc[nt0][3]);
                __half2 p2 = __floats2half2_rn(sacc[nt1][0], sacc[nt1][1]);
                __half2 p3 = __floats2half2_rn(sacc[nt1][2], sacc[nt1][3]);
                aP[0] = *(uint32_t*)&p0; aP[1] = *(uint32_t*)&p1;
                aP[2] = *(uint32_t*)&p2; aP[3] = *(uint32_t*)&p3;
            }
#pragma unroll
            for (int dp = 0; dp < 4; dp++) {
                const uint32_t addr = (rowV + 16 * ks) * 128 + (((2 * dp + vU) ^ rxv) << 4);
                uint32_t rv[4];
                ldmx4t(rv, tV + addr);
                mma_f16(oacc[2 * dp],     aP, rv);
                mma_f16(oacc[2 * dp + 1], aP, rv + 2);
            }
        }
        buf ^= 1;
    }

    // ---- epilogue: normalize, write fp16 plane
    const float inv0 = 1.0f / l0, inv1 = 1.0f / l1;
    const int row0 = b * SS + q0 + w * 16 + (lane >> 2);
    const int row1 = row0 + 8;
    const int dbase = h * HDIM + 2 * (lane & 3);
#pragma unroll
    for (int j = 0; j < 8; j++) {
        size_t a0 = (size_t)row0 * DD + dbase + 8 * j;
        size_t a1 = (size_t)row1 * DD + dbase + 8 * j;
        *(__half2*)&O_[a0] = __floats2half2_rn(oacc[j][0] * inv0, oacc[j][1] * inv0);
        *(__half2*)&O_[a1] = __floats2half2_rn(oacc[j][2] * inv1, oacc[j][3] * inv1);
    }
}

// ---------------------------------------------------------------------------
// Launch
// ---------------------------------------------------------------------------
extern "C" void kernel_launch(void* const* d_in, const int* in_sizes, int n_in,
                              void* d_out, int out_size)
{
    (void)out_size;
    const float* qkv[3]   = {nullptr, nullptr, nullptr};
    const int*   masks[2] = {nullptr, nullptr};
    const float* Ws[4]    = {nullptr, nullptr, nullptr, nullptr};
    const float* bs[4]    = {nullptr, nullptr, nullptr, nullptr};
    int nqkv = 0, nmask = 0, nW = 0, nb = 0;
    for (int i = 0; i < n_in; i++) {
        int sz = in_sizes[i];
        if (sz == MTOT * DD && nqkv < 3)      qkv[nqkv++] = (const float*)d_in[i];
        else if (sz == MTOT && nmask < 2)     masks[nmask++] = (const int*)d_in[i];
        else if (sz == DD * DD && nW < 4)     Ws[nW++] = (const float*)d_in[i];
        else if (sz == DD && nb < 4)          bs[nb++] = (const float*)d_in[i];
    }

    static int attr_done = 0;
    if (!attr_done) {
        cudaFuncSetAttribute(gemm_mma_kernel,
                             cudaFuncAttributeMaxDynamicSharedMemorySize, GSM2_BYTES);
        cudaFuncSetAttribute(attn_mma_kernel,
                             cudaFuncAttributeMaxDynamicSharedMemorySize, ATTN_SMEM);
        attr_done = 1;
    }

    int *gidx, *gcnt;
    __half *gq, *gk, *gv, *gW, *gpq, *gpk, *gpv, *ga;
    cudaGetSymbolAddress((void**)&gidx, g_idx);
    cudaGetSymbolAddress((void**)&gcnt, g_cnt);
    cudaGetSymbolAddress((void**)&gq, g_q);
    cudaGetSymbolAddress((void**)&gk, g_k);
    cudaGetSymbolAddress((void**)&gv, g_v);
    cudaGetSymbolAddress((void**)&gW, g_W);
    cudaGetSymbolAddress((void**)&gpq, g_pq);
    cudaGetSymbolAddress((void**)&gpk, g_pk);
    cudaGetSymbolAddress((void**)&gpv, g_pv);
    cudaGetSymbolAddress((void**)&ga, g_a);

    const int N8_ACT = (int)(ACT / 8);
    const int N8_W   = (int)(WN / 8);

    build_idx_kernel<<<BB, 1024>>>(masks[0], masks[1], gidx, gcnt);

    {
        ConvHArgs aa = {};
        aa.src[0] = qkv[0]; aa.dst[0] = gq;
        aa.src[1] = qkv[1]; aa.dst[1] = gk;
        aa.src[2] = qkv[2]; aa.dst[2] = gv;
        conv_half_multi<<<dim3((N8_ACT + 255) / 256, 3), 256>>>(aa, N8_ACT);

        ConvWArgs wa = {};
        for (int w = 0; w < 4; w++) {
            wa.src[w] = Ws[w];
            wa.hi[w]  = gW + (size_t)w * 2 * WN;
            wa.lo[w]  = gW + (size_t)w * 2 * WN + WN;
        }
        conv_wsplit_multi<<<dim3((N8_W + 255) / 256, 4), 256>>>(wa, N8_W);
    }

    const float QSCALE = 0.125f * 1.4426950408889634f;
    gemm_mma_kernel<<<dim3(DD / 128, MTOT / 256, 3), 512, GSM2_BYTES>>>(
        gq, gk, gv, gW, bs[0], bs[1], bs[2], QSCALE,
        nullptr, gpq, gpk, gpv, gidx, gcnt, 0b110);

    attn_mma_kernel<<<dim3(SS / 128, HH, BB), 256, ATTN_SMEM>>>(
        gpq, gpk, gpv, ga, gcnt);

    gemm_mma_kernel<<<dim3(DD / 128, MTOT / 256, 1), 512, GSM2_BYTES>>>(
        ga, ga, ga, gW + (size_t)3 * 2 * WN, bs[3], bs[3], bs[3], 1.0f,
        (float*)d_out, nullptr, nullptr, nullptr, nullptr, nullptr, 0);
}